// round 12
// baseline (speedup 1.0000x reference)
#include <cuda_runtime.h>
#include <cstdint>

#define BATCH 8
#define HEADS 8
#define NSEQ  4096
#define DM    512
#define DH    64
#define RP    256
#define MTOT  (BATCH*NSEQ)

// packed-A: quad q=((tm*nkt+tk)*32+lane); lane=(g<<2)+tig; elems e=hm+2hk at (m=16tm+g+8hm, k=8tk+tig+4hk)
// packed-B2: float4 q=((tn*nkt2+tk2)*32+lane); elems u*2+e at (n=8tn+g, k=16tk2+8u+tig+4e)
__device__ float g_xp[MTOT*DM];          // packed-A tf32(x)
__device__ float g_wp[4*DM*DM];          // packed-B2 tf32(wq,wk,wv,wo), nkt2=32
__device__ float g_Ep[HEADS*RP*NSEQ];    // packed-A tf32(E^T) per head
__device__ float g_Fp[HEADS*RP*NSEQ];
__device__ float g_Q [MTOT*DM];          // packed-A tf32 Q per bh (m=n,k=d), nkt=8
__device__ float g_K [MTOT*DM];          // packed-B2 tf32 K per bh (n=d,k=ns), nkt2=256
__device__ float g_V [MTOT*DM];
__device__ float g_KP[64*RP*DH];         // packed-B2 tf32 KP per bh (n=r,k=d), nkt2=4
__device__ float g_VP[64*RP*DH];         // packed-B2 tf32 VP per bh (n=d,k=r), nkt2=16
__device__ float g_AO[MTOT*DM];          // tf32 vals [m][512]

// ---------------- helpers ----------------
__device__ __forceinline__ float f2tf(float f) {
    unsigned u; asm("cvt.rna.tf32.f32 %0, %1;" : "=r"(u) : "f"(f));
    return __uint_as_float(u);
}
__device__ __forceinline__ void mma_tf32(float c[4], float a0, float a1, float a2, float a3,
                                         float b0, float b1) {
    asm volatile(
        "mma.sync.aligned.m16n8k8.row.col.f32.tf32.tf32.f32 "
        "{%0,%1,%2,%3},{%4,%5,%6,%7},{%8,%9},{%0,%1,%2,%3};\n"
        : "+f"(c[0]), "+f"(c[1]), "+f"(c[2]), "+f"(c[3])
        : "r"(__float_as_uint(a0)), "r"(__float_as_uint(a1)),
          "r"(__float_as_uint(a2)), "r"(__float_as_uint(a3)),
          "r"(__float_as_uint(b0)), "r"(__float_as_uint(b1)));
}
__device__ __forceinline__ uint32_t s2u(const void* p) {
    return (uint32_t)__cvta_generic_to_shared(p);
}
__device__ __forceinline__ void cpa16(uint32_t dst, const void* src) {
    asm volatile("cp.async.cg.shared.global [%0], [%1], 16;\n" :: "r"(dst), "l"(src));
}
__device__ __forceinline__ void cpcommit() {
    asm volatile("cp.async.commit_group;\n" ::: "memory");
}
template<int N> __device__ __forceinline__ void cpwait() {
    asm volatile("cp.async.wait_group %0;\n" :: "n"(N) : "memory");
}

// ---------------- pack kernels ----------------
__global__ void pack_a(const float* __restrict__ s, float* __restrict__ d,
                       int nkt, int sm, int sk, long sS, long dS) {
    s += blockIdx.y * sS; d += blockIdx.y * dS;
    int q = blockIdx.x * 256 + threadIdx.x;
    int tile = q >> 5, lane = q & 31;
    int tm = tile / nkt, tk = tile - tm * nkt;
    const float* p = s + (long)(tm * 16 + (lane >> 2)) * sm + (long)(tk * 8 + (lane & 3)) * sk;
    float4 v = make_float4(f2tf(p[0]), f2tf(p[8 * sm]), f2tf(p[4 * sk]), f2tf(p[8 * sm + 4 * sk]));
    *(float4*)(d + (long)q * 4) = v;
}
// packed-B2: one float4 per (tile2, lane) = B fragments for two consecutive k8
__global__ void pack_b2(const float* __restrict__ s0, const float* __restrict__ s1,
                        float* __restrict__ d, int nkt2, int sk) {
    const float* s = blockIdx.y ? s1 : s0;
    float* dd = d + (long)blockIdx.y * DM * DM;
    int q = blockIdx.x * 256 + threadIdx.x;
    int tile = q >> 5, lane = q & 31;
    int tn = tile / nkt2, tk2 = tile - tn * nkt2;
    const float* p = s + (long)(tk2 * 16 + (lane & 3)) * sk + tn * 8 + (lane >> 2);
    float4 v = make_float4(f2tf(p[0]), f2tf(p[4 * sk]), f2tf(p[8 * sk]), f2tf(p[12 * sk]));
    *(float4*)(dd + (long)q * 4) = v;
}

// =====================================================================
// qkv: C = x @ w (z = q/k/v).  BM=BN=128, BK=32, 3-stage, packed A+B2.
// Q written packed-A; K,V written packed-B2 (proj's B operand). All pre-tf32.
// =====================================================================
#define QSTG 8192
#define QKV_SMEM (3*QSTG*4)

__global__ __launch_bounds__(256, 2) void qkv_kernel()
{
    extern __shared__ float sm[];
    const float* wsrc = g_wp + blockIdx.z * DM * DM;

    const int m0t = blockIdx.y * 8;
    const int n0t = blockIdx.x * 16;
    const int tid = threadIdx.x, wid = tid >> 5, lane = tid & 31;
    const int g = lane >> 2, tig = lane & 3;
    const int tmB = (wid >> 1) * 2, tnB = (wid & 1) * 8;

    float acc[2][8][4] = {};

    auto load = [&](int s) {
        float* buf = sm + (s % 3) * QSTG;
        uint32_t ab = s2u(buf), bb = s2u(buf + 4096);
        #pragma unroll
        for (int l = 0; l < 4; l++) {
            int q = l * 256 + tid, tl = q >> 7, r = q & 127;
            cpa16(ab + (tl * 512 + r * 4) * 4, &g_xp[(long)(m0t + tl) * 8192 + s * 512 + r * 4]);
        }
        #pragma unroll
        for (int l = 0; l < 4; l++) {
            int q = l * 256 + tid, tl = q >> 6, r = q & 63;
            cpa16(bb + (tl * 256 + r * 4) * 4, &wsrc[(long)(n0t + tl) * 4096 + s * 256 + r * 4]);
        }
        cpcommit();
    };

    load(0); load(1);
    for (int s = 0; s < 16; s++) {
        if (s + 2 < 16) { load(s + 2); cpwait<2>(); }
        else if (s + 1 < 16) { cpwait<1>(); }
        else { cpwait<0>(); }
        __syncthreads();

        const float* A = sm + (s % 3) * QSTG;
        const float* B = A + 4096;
        #pragma unroll
        for (int ks2 = 0; ks2 < 2; ks2++) {
            float4 a00 = *(const float4*)&A[((tmB    ) * 4 + 2 * ks2    ) * 128 + lane * 4];
            float4 a01 = *(const float4*)&A[((tmB    ) * 4 + 2 * ks2 + 1) * 128 + lane * 4];
            float4 a10 = *(const float4*)&A[((tmB + 1) * 4 + 2 * ks2    ) * 128 + lane * 4];
            float4 a11 = *(const float4*)&A[((tmB + 1) * 4 + 2 * ks2 + 1) * 128 + lane * 4];
            #pragma unroll
            for (int nt = 0; nt < 8; nt++) {
                float4 bv = *(const float4*)&B[((tnB + nt) * 2 + ks2) * 128 + lane * 4];
                mma_tf32(acc[0][nt], a00.x, a00.y, a00.z, a00.w, bv.x, bv.y);
                mma_tf32(acc[0][nt], a01.x, a01.y, a01.z, a01.w, bv.z, bv.w);
                mma_tf32(acc[1][nt], a10.x, a10.y, a10.z, a10.w, bv.x, bv.y);
                mma_tf32(acc[1][nt], a11.x, a11.y, a11.z, a11.w, bv.z, bv.w);
            }
        }
        __syncthreads();
    }

    #pragma unroll
    for (int mt = 0; mt < 2; mt++)
    #pragma unroll
    for (int i = 0; i < 2; i++) {
        int m = m0t * 16 + (tmB + mt) * 16 + g + i * 8;
        int bb2 = m >> 12, ns = m & (NSEQ - 1);
        #pragma unroll
        for (int nt = 0; nt < 8; nt++) {
            int c = n0t * 8 + (tnB + nt) * 8 + tig * 2;
            int h = c >> 6, dh = c & 63;
            float v0 = f2tf(acc[mt][nt][i * 2]), v1 = f2tf(acc[mt][nt][i * 2 + 1]);
            long base = (long)(bb2 * HEADS + h) * (NSEQ * DH);
            if (blockIdx.z == 0) {
                int q = ((ns >> 4) * 8 + (dh >> 3)) * 32 + (ns & 7) * 4 + (dh & 3);
                int e = ((ns >> 3) & 1) + 2 * ((dh >> 2) & 1);
                g_Q[base + q * 4 + e] = v0;
                g_Q[base + q * 4 + e + 4] = v1;
            } else {
                // packed-B2 for proj: (n=dh, k=ns), nkt2=256
                float* outp = (blockIdx.z == 1) ? g_K : g_V;
                int pos = ((dh >> 3) * 256 + (ns >> 4)) * 128
                        + (((dh & 7) << 2) + (ns & 3)) * 4
                        + (((ns >> 3) & 1) << 1) + ((ns >> 2) & 1);
                outp[base + pos] = v0;
                outp[base + pos + 16] = v1;   // dh+1 -> lane+4
            }
        }
    }
}

// =====================================================================
// proj: KP[r,d] = sum_n E[n,r] K[n,d].  A packed-A (E/F); B packed-B2 K/V.
// KP written packed-B2 (n=r,k=d); VP written packed-B2 (n=d,k=r).
// =====================================================================
#define PSTG (4096 + 2048)
#define PRJ_SMEM (3*PSTG*4)

__global__ __launch_bounds__(256, 2) void proj_kernel()
{
    extern __shared__ float sm[];
    const int bh = blockIdx.y, h = bh & 7;
    const int r0t = blockIdx.x * 8;
    const float* Ap = (blockIdx.z == 0 ? g_Ep : g_Fp) + (long)h * RP * NSEQ;
    const float* S  = (blockIdx.z == 0 ? g_K : g_V) + (long)bh * NSEQ * DH;
    float* D = (blockIdx.z == 0 ? g_KP : g_VP) + bh * RP * DH;

    const int tid = threadIdx.x, wid = tid >> 5, lane = tid & 31;
    const int g = lane >> 2, tig = lane & 3;
    const int tmB = (wid >> 1) * 2, wn = (wid & 1) * 32;

    float acc[2][4][4] = {};

    auto load = [&](int s) {
        float* buf = sm + (s % 3) * PSTG;
        uint32_t ab = s2u(buf), bb = s2u(buf + 4096);
        #pragma unroll
        for (int l = 0; l < 4; l++) {
            int q = l * 256 + tid, tl = q >> 7, r = q & 127;
            cpa16(ab + (tl * 512 + r * 4) * 4, &Ap[(long)(r0t + tl) * 65536 + s * 512 + r * 4]);
        }
        #pragma unroll
        for (int l = 0; l < 2; l++) {
            int q4 = l * 256 + tid, tn = q4 >> 6, off = q4 & 63;
            cpa16(bb + q4 * 16, &S[(long)tn * 32768 + s * 256 + off * 4]);
        }
        cpcommit();
    };

    load(0); load(1);
    for (int s = 0; s < 128; s++) {
        if (s + 2 < 128) { load(s + 2); cpwait<2>(); }
        else if (s + 1 < 128) { cpwait<1>(); }
        else { cpwait<0>(); }
        __syncthreads();

        const float* A = sm + (s % 3) * PSTG;
        const float* B = A + 4096;
        #pragma unroll
        for (int ks2 = 0; ks2 < 2; ks2++) {
            float4 a00 = *(const float4*)&A[((tmB    ) * 4 + 2 * ks2    ) * 128 + lane * 4];
            float4 a01 = *(const float4*)&A[((tmB    ) * 4 + 2 * ks2 + 1) * 128 + lane * 4];
            float4 a10 = *(const float4*)&A[((tmB + 1) * 4 + 2 * ks2    ) * 128 + lane * 4];
            float4 a11 = *(const float4*)&A[((tmB + 1) * 4 + 2 * ks2 + 1) * 128 + lane * 4];
            #pragma unroll
            for (int nt = 0; nt < 4; nt++) {
                float4 bv = *(const float4*)&B[(((wn >> 3) + nt) * 2 + ks2) * 128 + lane * 4];
                mma_tf32(acc[0][nt], a00.x, a00.y, a00.z, a00.w, bv.x, bv.y);
                mma_tf32(acc[0][nt], a01.x, a01.y, a01.z, a01.w, bv.z, bv.w);
                mma_tf32(acc[1][nt], a10.x, a10.y, a10.z, a10.w, bv.x, bv.y);
                mma_tf32(acc[1][nt], a11.x, a11.y, a11.z, a11.w, bv.z, bv.w);
            }
        }
        __syncthreads();
    }

    #pragma unroll
    for (int mt = 0; mt < 2; mt++)
    #pragma unroll
    for (int i = 0; i < 2; i++) {
        int r = r0t * 16 + (tmB + mt) * 16 + g + i * 8;
        #pragma unroll
        for (int nt = 0; nt < 4; nt++) {
            int c = wn + nt * 8 + tig * 2;
            float v0 = f2tf(acc[mt][nt][i * 2]), v1 = f2tf(acc[mt][nt][i * 2 + 1]);
            if (blockIdx.z == 0) {
                // KP packed-B2: (n=r, k=c), nkt2=4
                int pos = ((r >> 3) * 4 + (c >> 4)) * 128
                        + (((r & 7) << 2) + (c & 3)) * 4
                        + (((c >> 3) & 1) << 1) + ((c >> 2) & 1);
                D[pos] = v0; D[pos + 4] = v1;      // c+1 -> lane+1
            } else {
                // VP packed-B2: (n=c, k=r), nkt2=16
                int pos = ((c >> 3) * 16 + (r >> 4)) * 128
                        + (((c & 7) << 2) + (r & 3)) * 4
                        + (((r >> 3) & 1) << 1) + ((r >> 2) & 1);
                D[pos] = v0; D[pos + 16] = v1;     // c+1 -> lane+4
            }
        }
    }
}

// =====================================================================
// attn: packed Q (A) + packed-B2 KP/VP.  grid (16, 64), 4 chunks/block.
// =====================================================================
#define AT_QS 4096
#define AT_KP 16384
#define AT_VP 16384
#define AT_PS (64*260)
#define AT_SMEM ((AT_QS + AT_KP + AT_VP + AT_PS + 256)*4)

__global__ __launch_bounds__(256) void attn_kernel()
{
    extern __shared__ float sm[];
    float* Qs   = sm;                 // packed-A, 4 tm x 8 tk x 128
    float* kps  = Qs + AT_QS;         // packed-B2, 32 tn x 4 tk2 x 128
    float* vps  = kps + AT_KP;        // packed-B2, 8 tn x 16 tk2 x 128
    float* Ps   = vps + AT_VP;        // [64][260]
    float* redM = Ps + AT_PS;
    float* redS = redM + 128;

    const int bh = blockIdx.y;
    const int tid = threadIdx.x;
    const int wid = tid >> 5, lane = tid & 31, g = lane >> 2, tig = lane & 3;
    const int wm = (wid >> 1) * 16, wn = wid & 1;
    const int tmq = wid >> 1;

    {
        const float* kpP = g_KP + (long)bh * RP * DH;
        const float* vpP = g_VP + (long)bh * RP * DH;
        #pragma unroll
        for (int l = 0; l < 16; l++) {
            int idx = (l * 256 + tid) * 4;
            *(float4*)&kps[idx] = *(const float4*)&kpP[idx];
            *(float4*)&vps[idx] = *(const float4*)&vpP[idx];
        }
    }

    const int b = bh >> 3, h = bh & 7;
    const float scale = 0.125f;

    for (int ci = 0; ci < 4; ci++) {
        const int n0 = blockIdx.x * 256 + ci * 64;
        const float* Qp = g_Q + (long)bh * (NSEQ * DH) + (n0 >> 4) * 1024;

        __syncthreads();
        #pragma unroll
        for (int l = 0; l < 4; l++) {
            int idx = (l * 256 + tid) * 4;
            *(float4*)&Qs[idx] = *(const float4*)&Qp[idx];
        }
        __syncthreads();

        // ---- phase 1: S = Q @ kp^T ----
        float acc[16][4] = {};
        #pragma unroll
        for (int ks2 = 0; ks2 < 4; ks2++) {
            float4 av0 = *(const float4*)&Qs[(tmq * 8 + 2 * ks2    ) * 128 + lane * 4];
            float4 av1 = *(const float4*)&Qs[(tmq * 8 + 2 * ks2 + 1) * 128 + lane * 4];
            #pragma unroll
            for (int nt = 0; nt < 16; nt++) {
                float4 bv = *(const float4*)&kps[((wn * 16 + nt) * 4 + ks2) * 128 + lane * 4];
                mma_tf32(acc[nt], av0.x, av0.y, av0.z, av0.w, bv.x, bv.y);
                mma_tf32(acc[nt], av1.x, av1.y, av1.z, av1.w, bv.z, bv.w);
            }
        }

        const int r0 = wm + g, r1 = r0 + 8;
        float mx0 = -1e30f, mx1 = -1e30f;
        #pragma unroll
        for (int nt = 0; nt < 16; nt++) {
            mx0 = fmaxf(mx0, fmaxf(acc[nt][0], acc[nt][1]));
            mx1 = fmaxf(mx1, fmaxf(acc[nt][2], acc[nt][3]));
        }
        mx0 = fmaxf(mx0, __shfl_xor_sync(0xffffffffu, mx0, 1));
        mx0 = fmaxf(mx0, __shfl_xor_sync(0xffffffffu, mx0, 2));
        mx1 = fmaxf(mx1, __shfl_xor_sync(0xffffffffu, mx1, 1));
        mx1 = fmaxf(mx1, __shfl_xor_sync(0xffffffffu, mx1, 2));
        if (tig == 0) { redM[r0 * 2 + wn] = mx0; redM[r1 * 2 + wn] = mx1; }
        __syncthreads();
        mx0 = fmaxf(redM[r0 * 2], redM[r0 * 2 + 1]) * scale;
        mx1 = fmaxf(redM[r1 * 2], redM[r1 * 2 + 1]) * scale;

        float s0 = 0.f, s1 = 0.f;
        #pragma unroll
        for (int nt = 0; nt < 16; nt++) {
            int c = wn * 128 + nt * 8 + tig * 2;
            float e0 = __expf(acc[nt][0] * scale - mx0);
            float e1 = __expf(acc[nt][1] * scale - mx0);
            s0 += e0 + e1;
            *(float2*)&Ps[r0 * 260 + c] = make_float2(f2tf(e0), f2tf(e1));
            float e2 = __expf(acc[nt][2] * scale - mx1);
            float e3 = __expf(acc[nt][3] * scale - mx1);
            s1 += e2 + e3;
            *(float2*)&Ps[r1 * 260 + c] = make_float2(f2tf(e2), f2tf(e3));
        }
        s0 += __shfl_xor_sync(0xffffffffu, s0, 1);
        s0 += __shfl_xor_sync(0xffffffffu, s0, 2);
        s1 += __shfl_xor_sync(0xffffffffu, s1, 1);
        s1 += __shfl_xor_sync(0xffffffffu, s1, 2);
        if (tig == 0) { redS[r0 * 2 + wn] = s0; redS[r1 * 2 + wn] = s1; }
        __syncthreads();

        // ---- phase 2: O = P @ vp ----
        float acc2[4][4] = {};
        #pragma unroll 4
        for (int ks2 = 0; ks2 < 16; ks2++) {
            int kb = ks2 * 16;
            float a0 = Ps[(wm + g)     * 260 + kb + tig];
            float a1 = Ps[(wm + g + 8) * 260 + kb + tig];
            float a2 = Ps[(wm + g)     * 260 + kb + tig + 4];
            float a3 = Ps[(wm + g + 8) * 260 + kb + tig + 4];
            float c0 = Ps[(wm + g)     * 260 + kb + 8 + tig];
            float c1 = Ps[(wm + g + 8) * 260 + kb + 8 + tig];
            float c2 = Ps[(wm + g)     * 260 + kb + 8 + tig + 4];
            float c3 = Ps[(wm + g + 8) * 260 + kb + 8 + tig + 4];
            #pragma unroll
            for (int nt = 0; nt < 4; nt++) {
                float4 bv = *(const float4*)&vps[((wn * 4 + nt) * 16 + ks2) * 128 + lane * 4];
                mma_tf32(acc2[nt], a0, a1, a2, a3, bv.x, bv.y);
                mma_tf32(acc2[nt], c0, c1, c2, c3, bv.z, bv.w);
            }
        }

        const float inv0 = __frcp_rn(redS[r0 * 2] + redS[r0 * 2 + 1]);
        const float inv1 = __frcp_rn(redS[r1 * 2] + redS[r1 * 2 + 1]);
        float* ao = g_AO + (long)(b * NSEQ + n0) * DM + h * DH;
        #pragma unroll
        for (int nt = 0; nt < 4; nt++) {
            int c = wn * 32 + nt * 8 + tig * 2;
            *(float2*)&ao[r0 * DM + c] =
                make_float2(f2tf(acc2[nt][0] * inv0), f2tf(acc2[nt][1] * inv0));
            *(float2*)&ao[r1 * DM + c] =
                make_float2(f2tf(acc2[nt][2] * inv1), f2tf(acc2[nt][3] * inv1));
        }
    }
}

// =====================================================================
// outproj: A raw pre-tf32 AO, B packed-B2 wo.
// =====================================================================
#define OA 4608
#define OSTG (OA + 4096)
#define OUT_SMEM (3*OSTG*4)

__global__ __launch_bounds__(256, 2) void outproj_kernel(
    const float* __restrict__ bo, float* __restrict__ out)
{
    extern __shared__ float sm[];
    const float* wsrc = g_wp + 3 * DM * DM;

    const int m0 = blockIdx.y * 128, n0t = blockIdx.x * 16;
    const int tid = threadIdx.x, wid = tid >> 5, lane = tid & 31;
    const int g = lane >> 2, tig = lane & 3;
    const int wm = (wid >> 1) * 32, tnB = (wid & 1) * 8;

    float acc[2][8][4] = {};

    auto load = [&](int s) {
        float* buf = sm + (s % 3) * OSTG;
        uint32_t ab = s2u(buf), bb = s2u(buf + OA);
        int k0 = s * 32;
        #pragma unroll
        for (int l = 0; l < 4; l++) {
            int r = l * 32 + (tid >> 3), c4 = (tid & 7) * 4;
            cpa16(ab + (r * 36 + c4) * 4, &g_AO[(long)(m0 + r) * DM + k0 + c4]);
        }
        #pragma unroll
        for (int l = 0; l < 4; l++) {
            int q = l * 256 + tid, tl = q >> 6, r = q & 63;
            cpa16(bb + (tl * 256 + r * 4) * 4, &wsrc[(long)(n0t + tl) * 4096 + s * 256 + r * 4]);
        }
        cpcommit();
    };

    load(0); load(1);
    for (int s = 0; s < 16; s++) {
        if (s + 2 < 16) { load(s + 2); cpwait<2>(); }
        else if (s + 1 < 16) { cpwait<1>(); }
        else { cpwait<0>(); }
        __syncthreads();

        const float* A = sm + (s % 3) * OSTG;
        const float* B = A + OA;
        #pragma unroll
        for (int ks2 = 0; ks2 < 2; ks2++) {
            float a[2][2][4];
            #pragma unroll
            for (int mt = 0; mt < 2; mt++)
            #pragma unroll
            for (int u = 0; u < 2; u++) {
                int r = wm + mt * 16, kb = ks2 * 16 + u * 8;
                a[mt][u][0] = A[(r + g)     * 36 + kb + tig];
                a[mt][u][1] = A[(r + g + 8) * 36 + kb + tig];
                a[mt][u][2] = A[(r + g)     * 36 + kb + tig + 4];
                a[mt][u][3] = A[(r + g + 8) * 36 + kb + tig + 4];
            }
            #pragma unroll
            for (int nt = 0; nt < 8; nt++) {
                float4 bv = *(const float4*)&B[((tnB + nt) * 2 + ks2) * 128 + lane * 4];
                mma_tf32(acc[0][nt], a[0][0][0], a[0][0][1], a[0][0][2], a[0][0][3], bv.x, bv.y);
                mma_tf32(acc[0][nt], a[0][1][0], a[0][1][1], a[0][1][2], a[0][1][3], bv.z, bv.w);
                mma_tf32(acc[1][nt], a[1][0][0], a[1][0][1], a[1][0][2], a[1][0][3], bv.x, bv.y);
                mma_tf32(acc[1][nt], a[1][1][0], a[1][1][1], a[1][1][2], a[1][1][3], bv.z, bv.w);
            }
        }
        __syncthreads();
    }

    #pragma unroll
    for (int mt = 0; mt < 2; mt++)
    #pragma unroll
    for (int i = 0; i < 2; i++) {
        int m = m0 + wm + mt * 16 + g + i * 8;
        #pragma unroll
        for (int nt = 0; nt < 8; nt++) {
            int c = n0t * 8 + (tnB + nt) * 8 + tig * 2;
            float2 bias = *(const float2*)&bo[c];
            *(float2*)&out[(long)m * DM + c] =
                make_float2(acc[mt][nt][i * 2] + bias.x, acc[mt][nt][i * 2 + 1] + bias.y);
        }
    }
}

// =====================================================================
extern "C" void kernel_launch(void* const* d_in, const int* in_sizes, int n_in,
                              void* d_out, int out_size)
{
    (void)in_sizes; (void)n_in; (void)out_size;
    const float* x  = (const float*)d_in[0];
    const float* wq = (const float*)d_in[1];
    const float* wk = (const float*)d_in[2];
    const float* wv = (const float*)d_in[3];
    const float* E  = (const float*)d_in[4];
    const float* F  = (const float*)d_in[5];
    const float* wo = (const float*)d_in[6];
    const float* bo = (const float*)d_in[7];
    float* out = (float*)d_out;

    cudaFuncSetAttribute(qkv_kernel,     cudaFuncAttributeMaxDynamicSharedMemorySize, QKV_SMEM);
    cudaFuncSetAttribute(proj_kernel,    cudaFuncAttributeMaxDynamicSharedMemorySize, PRJ_SMEM);
    cudaFuncSetAttribute(attn_kernel,    cudaFuncAttributeMaxDynamicSharedMemorySize, AT_SMEM);
    cudaFuncSetAttribute(outproj_kernel, cudaFuncAttributeMaxDynamicSharedMemorySize, OUT_SMEM);

    float *p_xp, *p_wp, *p_Ep, *p_Fp;
    cudaGetSymbolAddress((void**)&p_xp, g_xp);
    cudaGetSymbolAddress((void**)&p_wp, g_wp);
    cudaGetSymbolAddress((void**)&p_Ep, g_Ep);
    cudaGetSymbolAddress((void**)&p_Fp, g_Fp);

    // 5 pack launches, then qkv (6th: ncu -s 5 -c 1 captures it)
    pack_a<<<MTOT*DM/1024, 256>>>(x, p_xp, 64, DM, 1, 0, 0);
    pack_a<<<dim3(RP*NSEQ/1024, HEADS), 256>>>(E, p_Ep, 512, 1, RP,
                                               (long)NSEQ*RP, (long)RP*NSEQ);
    pack_a<<<dim3(RP*NSEQ/1024, HEADS), 256>>>(F, p_Fp, 512, 1, RP,
                                               (long)NSEQ*RP, (long)RP*NSEQ);
    pack_b2<<<dim3(DM*DM/1024, 2), 256>>>(wq, wk, p_wp,            32, DM);
    pack_b2<<<dim3(DM*DM/1024, 2), 256>>>(wv, wo, p_wp + 2*DM*DM,  32, DM);

    qkv_kernel    <<<dim3(4, 256, 3), 256, QKV_SMEM>>>();
    proj_kernel   <<<dim3(2, 64, 2),  256, PRJ_SMEM>>>();
    attn_kernel   <<<dim3(16, 64),    256, AT_SMEM>>>();
    outproj_kernel<<<dim3(4, 256),    256, OUT_SMEM>>>(bo, out);
}

// round 13
// speedup vs baseline: 1.0514x; 1.0514x over previous
#include <cuda_runtime.h>
#include <cstdint>

#define BATCH 8
#define HEADS 8
#define NSEQ  4096
#define DM    512
#define DH    64
#define RP    256
#define MTOT  (BATCH*NSEQ)

// packed-A: quad q=((tm*nkt+tk)*32 + g*4+tig); elems e=hm+2hk at (m=16tm+g+8hm, k=8tk+tig+4hk)
// packed-B: pair q=((tn*nkt+tk)*32 + g*4+tig); elems e at (n=8tn+g, k=8tk+tig+4e)
__device__ float g_xp[MTOT*DM];          // packed-A tf32(x)
__device__ float g_wp[4*DM*DM];          // packed-B tf32(wq,wk,wv,wo)
__device__ float g_Ep[HEADS*RP*NSEQ];    // packed-A tf32(E^T) per head
__device__ float g_Fp[HEADS*RP*NSEQ];
__device__ float g_Q [MTOT*DM];          // packed-A tf32 Q per bh (m=n,k=d), nkt=8
__device__ float g_K [MTOT*DM];          // tf32 vals [bh][n][64]
__device__ float g_V [MTOT*DM];
__device__ float g_KP[64*RP*DH];         // packed-B tf32 KP per bh (n=r,k=d), nkt=8
__device__ float g_VP[64*RP*DH];         // packed-B tf32 VP per bh (n=d,k=r), nkt=32
__device__ float g_AO[MTOT*DM];          // tf32 vals [m][512]

// ---------------- helpers ----------------
__device__ __forceinline__ float f2tf(float f) {
    unsigned u; asm("cvt.rna.tf32.f32 %0, %1;" : "=r"(u) : "f"(f));
    return __uint_as_float(u);
}
__device__ __forceinline__ void mma_tf32(float c[4], float a0, float a1, float a2, float a3,
                                         float b0, float b1) {
    asm volatile(
        "mma.sync.aligned.m16n8k8.row.col.f32.tf32.tf32.f32 "
        "{%0,%1,%2,%3},{%4,%5,%6,%7},{%8,%9},{%0,%1,%2,%3};\n"
        : "+f"(c[0]), "+f"(c[1]), "+f"(c[2]), "+f"(c[3])
        : "r"(__float_as_uint(a0)), "r"(__float_as_uint(a1)),
          "r"(__float_as_uint(a2)), "r"(__float_as_uint(a3)),
          "r"(__float_as_uint(b0)), "r"(__float_as_uint(b1)));
}
__device__ __forceinline__ uint32_t s2u(const void* p) {
    return (uint32_t)__cvta_generic_to_shared(p);
}
__device__ __forceinline__ void cpa16(uint32_t dst, const void* src) {
    asm volatile("cp.async.cg.shared.global [%0], [%1], 16;\n" :: "r"(dst), "l"(src));
}
__device__ __forceinline__ void cpcommit() {
    asm volatile("cp.async.commit_group;\n" ::: "memory");
}
template<int N> __device__ __forceinline__ void cpwait() {
    asm volatile("cp.async.wait_group %0;\n" :: "n"(N) : "memory");
}

// ---------------- pack kernels ----------------
__global__ void pack_a(const float* __restrict__ s, float* __restrict__ d,
                       int nkt, int sm, int sk, long sS, long dS) {
    s += blockIdx.y * sS; d += blockIdx.y * dS;
    int q = blockIdx.x * 256 + threadIdx.x;
    int tile = q >> 5, lane = q & 31;
    int tm = tile / nkt, tk = tile - tm * nkt;
    const float* p = s + (long)(tm * 16 + (lane >> 2)) * sm + (long)(tk * 8 + (lane & 3)) * sk;
    float4 v = make_float4(f2tf(p[0]), f2tf(p[8 * sm]), f2tf(p[4 * sk]), f2tf(p[8 * sm + 4 * sk]));
    *(float4*)(d + (long)q * 4) = v;
}
__global__ void pack_b(const float* __restrict__ s0, const float* __restrict__ s1,
                       float* __restrict__ d, int nkt, int sk) {
    const float* s = blockIdx.y ? s1 : s0;
    float* dd = d + (long)blockIdx.y * DM * DM;
    int q = blockIdx.x * 256 + threadIdx.x;
    int tile = q >> 5, lane = q & 31;
    int tn = tile / nkt, tk = tile - tn * nkt;
    const float* p = s + (long)(tk * 8 + (lane & 3)) * sk + tn * 8 + (lane >> 2);
    *(float2*)(dd + (long)q * 2) = make_float2(f2tf(p[0]), f2tf(p[4 * sk]));
}

// =====================================================================
// qkv: C = x @ w (z = q/k/v).  BM=BN=128, BK=32, 3-stage, packed A+B.
// Single barrier per stage: cpwait -> sync -> load(s+2) -> mma(s).
// Q written packed-A pre-tf32; K,V head-split pre-tf32.
// =====================================================================
#define QSTG 8192
#define QKV_SMEM (3*QSTG*4)

__global__ __launch_bounds__(256, 2) void qkv_kernel()
{
    extern __shared__ float sm[];
    const float* wsrc = g_wp + blockIdx.z * DM * DM;

    const int m0t = blockIdx.y * 8;
    const int n0t = blockIdx.x * 16;
    const int tid = threadIdx.x, wid = tid >> 5, lane = tid & 31;
    const int g = lane >> 2, tig = lane & 3;
    const int tmB = (wid >> 1) * 2, tnB = (wid & 1) * 8;

    float acc[2][8][4] = {};

    auto load = [&](int s) {
        float* buf = sm + (s % 3) * QSTG;
        uint32_t ab = s2u(buf), bb = s2u(buf + 4096);
        #pragma unroll
        for (int l = 0; l < 4; l++) {
            int q = l * 256 + tid, tl = q >> 7, r = q & 127;
            cpa16(ab + (tl * 512 + r * 4) * 4, &g_xp[(long)(m0t + tl) * 8192 + s * 512 + r * 4]);
        }
        #pragma unroll
        for (int l = 0; l < 4; l++) {
            int q = l * 256 + tid, tl = q >> 6, r = q & 63;
            cpa16(bb + (tl * 256 + r * 4) * 4, &wsrc[(long)(n0t + tl) * 4096 + s * 256 + r * 4]);
        }
        cpcommit();
    };

    load(0); load(1);
    for (int s = 0; s < 16; s++) {
        if (s + 1 < 16) { cpwait<1>(); } else { cpwait<0>(); }
        __syncthreads();
        if (s + 2 < 16) load(s + 2);

        const float* A = sm + (s % 3) * QSTG;
        const float* B = A + 4096;
        #pragma unroll
        for (int ks = 0; ks < 4; ks++) {
            float4 a0 = *(const float4*)&A[((tmB    ) * 4 + ks) * 128 + lane * 4];
            float4 a1 = *(const float4*)&A[((tmB + 1) * 4 + ks) * 128 + lane * 4];
            #pragma unroll
            for (int nt = 0; nt < 8; nt++) {
                float2 bv = *(const float2*)&B[((tnB + nt) * 4 + ks) * 64 + lane * 2];
                mma_tf32(acc[0][nt], a0.x, a0.y, a0.z, a0.w, bv.x, bv.y);
                mma_tf32(acc[1][nt], a1.x, a1.y, a1.z, a1.w, bv.x, bv.y);
            }
        }
    }

    #pragma unroll
    for (int mt = 0; mt < 2; mt++)
    #pragma unroll
    for (int i = 0; i < 2; i++) {
        int m = m0t * 16 + (tmB + mt) * 16 + g + i * 8;
        int bb2 = m >> 12, ns = m & (NSEQ - 1);
        #pragma unroll
        for (int nt = 0; nt < 8; nt++) {
            int c = n0t * 8 + (tnB + nt) * 8 + tig * 2;
            int h = c >> 6, dh = c & 63;
            float v0 = f2tf(acc[mt][nt][i * 2]), v1 = f2tf(acc[mt][nt][i * 2 + 1]);
            long bhb = (long)(bb2 * HEADS + h);
            if (blockIdx.z == 0) {
                int q = ((ns >> 4) * 8 + (dh >> 3)) * 32 + (ns & 7) * 4 + (dh & 3);
                int e = ((ns >> 3) & 1) + 2 * ((dh >> 2) & 1);
                float* Qp = g_Q + bhb * (NSEQ * DH);
                Qp[q * 4 + e] = v0;
                Qp[q * 4 + e + 4] = v1;
            } else {
                float* outp = (blockIdx.z == 1) ? g_K : g_V;
                *(float2*)&outp[(bhb * NSEQ + ns) * DH + dh] = make_float2(v0, v1);
            }
        }
    }
}

// =====================================================================
// proj: KP[r,d] = sum_n E[n,r] K[n,d].  A packed (E/F); B raw pre-tf32.
// Single barrier per stage (128 stages).  KP/VP written packed-B pre-tf32.
// =====================================================================
#define PSTG (4096 + 32*72)
#define PRJ_SMEM (3*PSTG*4)

__global__ __launch_bounds__(256, 2) void proj_kernel()
{
    extern __shared__ float sm[];
    const int bh = blockIdx.y, h = bh & 7;
    const int r0t = blockIdx.x * 8;
    const float* Ap = (blockIdx.z == 0 ? g_Ep : g_Fp) + (long)h * RP * NSEQ;
    const float* S  = (blockIdx.z == 0 ? g_K : g_V) + (long)bh * NSEQ * DH;
    float* D = (blockIdx.z == 0 ? g_KP : g_VP) + bh * RP * DH;

    const int tid = threadIdx.x, wid = tid >> 5, lane = tid & 31;
    const int g = lane >> 2, tig = lane & 3;
    const int tmB = (wid >> 1) * 2, wn = (wid & 1) * 32;

    float acc[2][4][4] = {};

    auto load = [&](int s) {
        float* buf = sm + (s % 3) * PSTG;
        uint32_t ab = s2u(buf), bb = s2u(buf + 4096);
        #pragma unroll
        for (int l = 0; l < 4; l++) {
            int q = l * 256 + tid, tl = q >> 7, r = q & 127;
            cpa16(ab + (tl * 512 + r * 4) * 4, &Ap[(long)(r0t + tl) * 65536 + s * 512 + r * 4]);
        }
        #pragma unroll
        for (int l = 0; l < 2; l++) {
            int rr = l * 16 + (tid >> 4), c4 = (tid & 15) * 4;
            cpa16(bb + (rr * 72 + c4) * 4, &S[(long)(s * 32 + rr) * DH + c4]);
        }
        cpcommit();
    };

    load(0); load(1);
    for (int s = 0; s < 128; s++) {
        if (s + 1 < 128) { cpwait<1>(); } else { cpwait<0>(); }
        __syncthreads();
        if (s + 2 < 128) load(s + 2);

        const float* A = sm + (s % 3) * PSTG;
        const float* B = A + 4096;
        #pragma unroll
        for (int ks = 0; ks < 4; ks++) {
            int kb = ks * 8;
            float4 a0 = *(const float4*)&A[((tmB    ) * 4 + ks) * 128 + lane * 4];
            float4 a1 = *(const float4*)&A[((tmB + 1) * 4 + ks) * 128 + lane * 4];
            #pragma unroll
            for (int nt = 0; nt < 4; nt++) {
                float b0 = B[(kb + tig)     * 72 + wn + nt * 8 + g];
                float b1 = B[(kb + tig + 4) * 72 + wn + nt * 8 + g];
                mma_tf32(acc[0][nt], a0.x, a0.y, a0.z, a0.w, b0, b1);
                mma_tf32(acc[1][nt], a1.x, a1.y, a1.z, a1.w, b0, b1);
            }
        }
    }

    #pragma unroll
    for (int mt = 0; mt < 2; mt++)
    #pragma unroll
    for (int i = 0; i < 2; i++) {
        int r = r0t * 16 + (tmB + mt) * 16 + g + i * 8;
        #pragma unroll
        for (int nt = 0; nt < 4; nt++) {
            int c = wn + nt * 8 + tig * 2;
            float v0 = f2tf(acc[mt][nt][i * 2]), v1 = f2tf(acc[mt][nt][i * 2 + 1]);
            if (blockIdx.z == 0) {
                int q = ((r >> 3) * 8 + (c >> 3)) * 32 + (r & 7) * 4 + (c & 3);
                int e = (c >> 2) & 1;
                D[q * 2 + e] = v0;
                D[(q + 1) * 2 + e] = v1;
            } else {
                int q = ((c >> 3) * 32 + (r >> 3)) * 32 + (c & 7) * 4 + (r & 3);
                int e = (r >> 2) & 1;
                D[q * 2 + e] = v0;
                D[q * 2 + e + 8] = v1;
            }
        }
    }
}

// =====================================================================
// attn: packed Q/KP/VP; double-buffered Q via cp.async (prefetch next chunk).
// grid (16, 64), 4 chunks of 64 Q rows per block.
// =====================================================================
#define AT_QS 4096
#define AT_KP 16384
#define AT_VP 16384
#define AT_PS (64*260)
#define AT_SMEM ((2*AT_QS + AT_KP + AT_VP + AT_PS + 256)*4)

__global__ __launch_bounds__(256) void attn_kernel()
{
    extern __shared__ float sm[];
    float* Qs   = sm;                 // 2 x packed-A (4 tm x 8 tk x 128)
    float* kps  = Qs + 2 * AT_QS;     // packed-B, 32 tn x 8 tk x 64
    float* vps  = kps + AT_KP;        // packed-B, 8 tn x 32 tk x 64
    float* Ps   = vps + AT_VP;        // [64][260]
    float* redM = Ps + AT_PS;
    float* redS = redM + 128;

    const int bh = blockIdx.y;
    const int tid = threadIdx.x;
    const int wid = tid >> 5, lane = tid & 31, g = lane >> 2, tig = lane & 3;
    const int wm = (wid >> 1) * 16, wn = wid & 1;
    const int tmq = wid >> 1;

    {
        const float* kpP = g_KP + (long)bh * RP * DH;
        const float* vpP = g_VP + (long)bh * RP * DH;
        #pragma unroll
        for (int l = 0; l < 16; l++) {
            int idx = (l * 256 + tid) * 4;
            *(float4*)&kps[idx] = *(const float4*)&kpP[idx];
            *(float4*)&vps[idx] = *(const float4*)&vpP[idx];
        }
    }

    const float* Qbase = g_Q + (long)bh * (NSEQ * DH) + (blockIdx.x * 256 >> 4) * 1024;
    // prefetch Q chunk 0
    {
        uint32_t qb = s2u(Qs);
        #pragma unroll
        for (int l = 0; l < 4; l++) {
            int idx = (l * 256 + tid) * 4;
            cpa16(qb + idx * 4, &Qbase[idx]);
        }
        cpcommit();
    }

    const int b = bh >> 3, h = bh & 7;
    const float scale = 0.125f;

    for (int ci = 0; ci < 4; ci++) {
        const int n0 = blockIdx.x * 256 + ci * 64;

        cpwait<0>();
        __syncthreads();   // Q(ci) resident; prev-iter Ps/red reads done

        if (ci + 1 < 4) {  // prefetch Q(ci+1) into other buffer
            uint32_t qb = s2u(Qs + ((ci + 1) & 1) * AT_QS);
            const float* Qn = Qbase + (ci + 1) * AT_QS;
            #pragma unroll
            for (int l = 0; l < 4; l++) {
                int idx = (l * 256 + tid) * 4;
                cpa16(qb + idx * 4, &Qn[idx]);
            }
            cpcommit();
        }

        const float* Qc = Qs + (ci & 1) * AT_QS;

        // ---- phase 1: S = Q @ kp^T ----
        float acc[16][4] = {};
        #pragma unroll
        for (int ks = 0; ks < 8; ks++) {
            float4 av = *(const float4*)&Qc[(tmq * 8 + ks) * 128 + lane * 4];
            #pragma unroll
            for (int nt = 0; nt < 16; nt++) {
                float2 bv = *(const float2*)&kps[((wn * 16 + nt) * 8 + ks) * 64 + lane * 2];
                mma_tf32(acc[nt], av.x, av.y, av.z, av.w, bv.x, bv.y);
            }
        }

        const int r0 = wm + g, r1 = r0 + 8;
        float mx0 = -1e30f, mx1 = -1e30f;
        #pragma unroll
        for (int nt = 0; nt < 16; nt++) {
            mx0 = fmaxf(mx0, fmaxf(acc[nt][0], acc[nt][1]));
            mx1 = fmaxf(mx1, fmaxf(acc[nt][2], acc[nt][3]));
        }
        mx0 = fmaxf(mx0, __shfl_xor_sync(0xffffffffu, mx0, 1));
        mx0 = fmaxf(mx0, __shfl_xor_sync(0xffffffffu, mx0, 2));
        mx1 = fmaxf(mx1, __shfl_xor_sync(0xffffffffu, mx1, 1));
        mx1 = fmaxf(mx1, __shfl_xor_sync(0xffffffffu, mx1, 2));
        if (tig == 0) { redM[r0 * 2 + wn] = mx0; redM[r1 * 2 + wn] = mx1; }
        __syncthreads();
        mx0 = fmaxf(redM[r0 * 2], redM[r0 * 2 + 1]) * scale;
        mx1 = fmaxf(redM[r1 * 2], redM[r1 * 2 + 1]) * scale;

        float s0 = 0.f, s1 = 0.f;
        #pragma unroll
        for (int nt = 0; nt < 16; nt++) {
            int c = wn * 128 + nt * 8 + tig * 2;
            float e0 = __expf(acc[nt][0] * scale - mx0);
            float e1 = __expf(acc[nt][1] * scale - mx0);
            s0 += e0 + e1;
            *(float2*)&Ps[r0 * 260 + c] = make_float2(f2tf(e0), f2tf(e1));
            float e2 = __expf(acc[nt][2] * scale - mx1);
            float e3 = __expf(acc[nt][3] * scale - mx1);
            s1 += e2 + e3;
            *(float2*)&Ps[r1 * 260 + c] = make_float2(f2tf(e2), f2tf(e3));
        }
        s0 += __shfl_xor_sync(0xffffffffu, s0, 1);
        s0 += __shfl_xor_sync(0xffffffffu, s0, 2);
        s1 += __shfl_xor_sync(0xffffffffu, s1, 1);
        s1 += __shfl_xor_sync(0xffffffffu, s1, 2);
        if (tig == 0) { redS[r0 * 2 + wn] = s0; redS[r1 * 2 + wn] = s1; }
        __syncthreads();

        // ---- phase 2: O = P @ vp ----
        float acc2[4][4] = {};
        #pragma unroll 8
        for (int ks = 0; ks < 32; ks++) {
            int kb = ks * 8;
            float a0 = Ps[(wm + g)     * 260 + kb + tig];
            float a1 = Ps[(wm + g + 8) * 260 + kb + tig];
            float a2 = Ps[(wm + g)     * 260 + kb + tig + 4];
            float a3 = Ps[(wm + g + 8) * 260 + kb + tig + 4];
            #pragma unroll
            for (int nt = 0; nt < 4; nt++) {
                float2 bv = *(const float2*)&vps[((wn * 4 + nt) * 32 + ks) * 64 + lane * 2];
                mma_tf32(acc2[nt], a0, a1, a2, a3, bv.x, bv.y);
            }
        }

        const float inv0 = __frcp_rn(redS[r0 * 2] + redS[r0 * 2 + 1]);
        const float inv1 = __frcp_rn(redS[r1 * 2] + redS[r1 * 2 + 1]);
        float* ao = g_AO + (long)(b * NSEQ + n0) * DM + h * DH;
        #pragma unroll
        for (int nt = 0; nt < 4; nt++) {
            int c = wn * 32 + nt * 8 + tig * 2;
            *(float2*)&ao[r0 * DM + c] =
                make_float2(f2tf(acc2[nt][0] * inv0), f2tf(acc2[nt][1] * inv0));
            *(float2*)&ao[r1 * DM + c] =
                make_float2(f2tf(acc2[nt][2] * inv1), f2tf(acc2[nt][3] * inv1));
        }
    }
}

// =====================================================================
// outproj: A raw pre-tf32 AO, B packed wo.  Single barrier per stage.
// =====================================================================
#define OA 4608
#define OSTG (OA + 4096)
#define OUT_SMEM (3*OSTG*4)

__global__ __launch_bounds__(256, 2) void outproj_kernel(
    const float* __restrict__ bo, float* __restrict__ out)
{
    extern __shared__ float sm[];
    const float* wsrc = g_wp + 3 * DM * DM;

    const int m0 = blockIdx.y * 128, n0t = blockIdx.x * 16;
    const int tid = threadIdx.x, wid = tid >> 5, lane = tid & 31;
    const int g = lane >> 2, tig = lane & 3;
    const int wm = (wid >> 1) * 32, tnB = (wid & 1) * 8;

    float acc[2][8][4] = {};

    auto load = [&](int s) {
        float* buf = sm + (s % 3) * OSTG;
        uint32_t ab = s2u(buf), bb = s2u(buf + OA);
        int k0 = s * 32;
        #pragma unroll
        for (int l = 0; l < 4; l++) {
            int r = l * 32 + (tid >> 3), c4 = (tid & 7) * 4;
            cpa16(ab + (r * 36 + c4) * 4, &g_AO[(long)(m0 + r) * DM + k0 + c4]);
        }
        #pragma unroll
        for (int l = 0; l < 4; l++) {
            int q = l * 256 + tid, tl = q >> 6, r = q & 63;
            cpa16(bb + (tl * 256 + r * 4) * 4, &wsrc[(long)(n0t + tl) * 4096 + s * 256 + r * 4]);
        }
        cpcommit();
    };

    load(0); load(1);
    for (int s = 0; s < 16; s++) {
        if (s + 1 < 16) { cpwait<1>(); } else { cpwait<0>(); }
        __syncthreads();
        if (s + 2 < 16) load(s + 2);

        const float* A = sm + (s % 3) * OSTG;
        const float* B = A + OA;
        #pragma unroll
        for (int ks = 0; ks < 4; ks++) {
            int kb = ks * 8;
            float a[2][4];
            #pragma unroll
            for (int mt = 0; mt < 2; mt++) {
                int r = wm + mt * 16;
                a[mt][0] = A[(r + g)     * 36 + kb + tig];
                a[mt][1] = A[(r + g + 8) * 36 + kb + tig];
                a[mt][2] = A[(r + g)     * 36 + kb + tig + 4];
                a[mt][3] = A[(r + g + 8) * 36 + kb + tig + 4];
            }
            #pragma unroll
            for (int nt = 0; nt < 8; nt++) {
                float2 bv = *(const float2*)&B[((tnB + nt) * 4 + ks) * 64 + lane * 2];
                mma_tf32(acc[0][nt], a[0][0], a[0][1], a[0][2], a[0][3], bv.x, bv.y);
                mma_tf32(acc[1][nt], a[1][0], a[1][1], a[1][2], a[1][3], bv.x, bv.y);
            }
        }
    }

    #pragma unroll
    for (int mt = 0; mt < 2; mt++)
    #pragma unroll
    for (int i = 0; i < 2; i++) {
        int m = m0 + wm + mt * 16 + g + i * 8;
        #pragma unroll
        for (int nt = 0; nt < 8; nt++) {
            int c = n0t * 8 + (tnB + nt) * 8 + tig * 2;
            float2 bias = *(const float2*)&bo[c];
            *(float2*)&out[(long)m * DM + c] =
                make_float2(acc[mt][nt][i * 2] + bias.x, acc[mt][nt][i * 2 + 1] + bias.y);
        }
    }
}

// =====================================================================
extern "C" void kernel_launch(void* const* d_in, const int* in_sizes, int n_in,
                              void* d_out, int out_size)
{
    (void)in_sizes; (void)n_in; (void)out_size;
    const float* x  = (const float*)d_in[0];
    const float* wq = (const float*)d_in[1];
    const float* wk = (const float*)d_in[2];
    const float* wv = (const float*)d_in[3];
    const float* E  = (const float*)d_in[4];
    const float* F  = (const float*)d_in[5];
    const float* wo = (const float*)d_in[6];
    const float* bo = (const float*)d_in[7];
    float* out = (float*)d_out;

    cudaFuncSetAttribute(qkv_kernel,     cudaFuncAttributeMaxDynamicSharedMemorySize, QKV_SMEM);
    cudaFuncSetAttribute(proj_kernel,    cudaFuncAttributeMaxDynamicSharedMemorySize, PRJ_SMEM);
    cudaFuncSetAttribute(attn_kernel,    cudaFuncAttributeMaxDynamicSharedMemorySize, AT_SMEM);
    cudaFuncSetAttribute(outproj_kernel, cudaFuncAttributeMaxDynamicSharedMemorySize, OUT_SMEM);

    float *p_xp, *p_wp, *p_Ep, *p_Fp;
    cudaGetSymbolAddress((void**)&p_xp, g_xp);
    cudaGetSymbolAddress((void**)&p_wp, g_wp);
    cudaGetSymbolAddress((void**)&p_Ep, g_Ep);
    cudaGetSymbolAddress((void**)&p_Fp, g_Fp);

    // 5 pack launches, then qkv (6th: ncu -s 5 -c 1 captures it)
    pack_a<<<MTOT*DM/1024, 256>>>(x, p_xp, 64, DM, 1, 0, 0);
    pack_a<<<dim3(RP*NSEQ/1024, HEADS), 256>>>(E, p_Ep, 512, 1, RP,
                                               (long)NSEQ*RP, (long)RP*NSEQ);
    pack_a<<<dim3(RP*NSEQ/1024, HEADS), 256>>>(F, p_Fp, 512, 1, RP,
                                               (long)NSEQ*RP, (long)RP*NSEQ);
    pack_b<<<dim3(DM*DM/512, 2), 256>>>(wq, wk, p_wp,            64, DM);
    pack_b<<<dim3(DM*DM/512, 2), 256>>>(wv, wo, p_wp + 2*DM*DM,  64, DM);

    qkv_kernel    <<<dim3(4, 256, 3), 256, QKV_SMEM>>>();
    proj_kernel   <<<dim3(2, 64, 2),  256, PRJ_SMEM>>>();
    attn_kernel   <<<dim3(16, 64),    256, AT_SMEM>>>();
    outproj_kernel<<<dim3(4, 256),    256, OUT_SMEM>>>(bo, out);
}

// round 14
// speedup vs baseline: 1.0679x; 1.0157x over previous
#include <cuda_runtime.h>
#include <cstdint>

#define BATCH 8
#define HEADS 8
#define NSEQ  4096
#define DM    512
#define DH    64
#define RP    256
#define MTOT  (BATCH*NSEQ)

// packed-A: quad q=((tm*nkt+tk)*32 + g*4+tig); elems e=hm+2hk at (m=16tm+g+8hm, k=8tk+tig+4hk)
// packed-B: pair q=((tn*nkt+tk)*32 + g*4+tig); elems e at (n=8tn+g, k=8tk+tig+4e)
__device__ float g_xp[MTOT*DM];          // packed-A tf32(x)
__device__ float g_wp[4*DM*DM];          // packed-B tf32(wq,wk,wv,wo)
__device__ float g_Ep[HEADS*RP*NSEQ];    // packed-A tf32(E^T) per head
__device__ float g_Fp[HEADS*RP*NSEQ];
__device__ float g_Q [MTOT*DM];          // packed-A tf32 Q per bh (m=n,k=d), nkt=8
__device__ float g_K [MTOT*DM];          // tf32 vals [bh][n][64]
__device__ float g_V [MTOT*DM];
__device__ float g_KP[64*RP*DH];         // packed-B tf32 KP per bh (n=r,k=d), nkt=8
__device__ float g_VP[64*RP*DH];         // packed-B tf32 VP per bh (n=d,k=r), nkt=32
__device__ float g_AO[MTOT*DM];          // tf32 vals [m][512]

// ---------------- helpers ----------------
__device__ __forceinline__ float f2tf(float f) {
    unsigned u; asm("cvt.rna.tf32.f32 %0, %1;" : "=r"(u) : "f"(f));
    return __uint_as_float(u);
}
__device__ __forceinline__ void mma_tf32(float c[4], float a0, float a1, float a2, float a3,
                                         float b0, float b1) {
    asm volatile(
        "mma.sync.aligned.m16n8k8.row.col.f32.tf32.tf32.f32 "
        "{%0,%1,%2,%3},{%4,%5,%6,%7},{%8,%9},{%0,%1,%2,%3};\n"
        : "+f"(c[0]), "+f"(c[1]), "+f"(c[2]), "+f"(c[3])
        : "r"(__float_as_uint(a0)), "r"(__float_as_uint(a1)),
          "r"(__float_as_uint(a2)), "r"(__float_as_uint(a3)),
          "r"(__float_as_uint(b0)), "r"(__float_as_uint(b1)));
}
__device__ __forceinline__ uint32_t s2u(const void* p) {
    return (uint32_t)__cvta_generic_to_shared(p);
}
__device__ __forceinline__ void cpa16(uint32_t dst, const void* src) {
    asm volatile("cp.async.cg.shared.global [%0], [%1], 16;\n" :: "r"(dst), "l"(src));
}
__device__ __forceinline__ void cpcommit() {
    asm volatile("cp.async.commit_group;\n" ::: "memory");
}
template<int N> __device__ __forceinline__ void cpwait() {
    asm volatile("cp.async.wait_group %0;\n" :: "n"(N) : "memory");
}

// ---------------- pack kernels ----------------
__global__ void pack_a(const float* __restrict__ s, float* __restrict__ d,
                       int nkt, int sm, int sk, long sS, long dS) {
    s += blockIdx.y * sS; d += blockIdx.y * dS;
    int q = blockIdx.x * 256 + threadIdx.x;
    int tile = q >> 5, lane = q & 31;
    int tm = tile / nkt, tk = tile - tm * nkt;
    const float* p = s + (long)(tm * 16 + (lane >> 2)) * sm + (long)(tk * 8 + (lane & 3)) * sk;
    float4 v = make_float4(f2tf(p[0]), f2tf(p[8 * sm]), f2tf(p[4 * sk]), f2tf(p[8 * sm + 4 * sk]));
    *(float4*)(d + (long)q * 4) = v;
}
__global__ void pack_b(const float* __restrict__ s0, const float* __restrict__ s1,
                       float* __restrict__ d, int nkt, int sk) {
    const float* s = blockIdx.y ? s1 : s0;
    float* dd = d + (long)blockIdx.y * DM * DM;
    int q = blockIdx.x * 256 + threadIdx.x;
    int tile = q >> 5, lane = q & 31;
    int tn = tile / nkt, tk = tile - tn * nkt;
    const float* p = s + (long)(tk * 8 + (lane & 3)) * sk + tn * 8 + (lane >> 2);
    *(float2*)(dd + (long)q * 2) = make_float2(f2tf(p[0]), f2tf(p[4 * sk]));
}

#define QSTG 8192
#define QKV_SMEM (3*QSTG*4)
#define PSTG (4096 + 32*72)

// =====================================================================
// qkv_kv: K,V slices of qkv (z: 0->K, 1->V).  Also packs a distributed
// slice of E/F (same math as pack_a).  grid (4, 256, 2).
// =====================================================================
__global__ __launch_bounds__(256, 2) void qkv_kv(
    const float* __restrict__ E, const float* __restrict__ F)
{
    extern __shared__ float sm[];
    const float* wsrc = g_wp + (blockIdx.z + 1) * DM * DM;
    float* outp = blockIdx.z ? g_V : g_K;

    const int m0t = blockIdx.y * 8;
    const int n0t = blockIdx.x * 16;
    const int tid = threadIdx.x, wid = tid >> 5, lane = tid & 31;
    const int g = lane >> 2, tig = lane & 3;
    const int tmB = (wid >> 1) * 2, tnB = (wid & 1) * 8;

    float acc[2][8][4] = {};

    auto load = [&](int s) {
        float* buf = sm + (s % 3) * QSTG;
        uint32_t ab = s2u(buf), bb = s2u(buf + 4096);
        #pragma unroll
        for (int l = 0; l < 4; l++) {
            int q = l * 256 + tid, tl = q >> 7, r = q & 127;
            cpa16(ab + (tl * 512 + r * 4) * 4, &g_xp[(long)(m0t + tl) * 8192 + s * 512 + r * 4]);
        }
        #pragma unroll
        for (int l = 0; l < 4; l++) {
            int q = l * 256 + tid, tl = q >> 6, r = q & 63;
            cpa16(bb + (tl * 256 + r * 4) * 4, &wsrc[(long)(n0t + tl) * 4096 + s * 256 + r * 4]);
        }
        cpcommit();
    };

    load(0); load(1);

    // distributed E/F pack: 2048 quads per CTA (8 per thread), pack_a math
    {
        int cid = blockIdx.x + 4 * blockIdx.y + 1024 * blockIdx.z;
        #pragma unroll
        for (int l = 0; l < 8; l++) {
            long q  = (long)cid * 2048 + l * 256 + tid;
            int arr = (int)(q >> 21);
            long qa = q & ((1L << 21) - 1);
            int hh  = (int)(qa >> 18);
            long qh = qa & ((1L << 18) - 1);
            int tile = (int)(qh >> 5), ln = (int)(qh & 31);
            int tm = tile >> 9, tk = tile & 511;
            const float* s = (arr ? F : E) + (long)hh * NSEQ * RP
                           + (tm * 16 + (ln >> 2)) + (long)(tk * 8 + (ln & 3)) * RP;
            float4 v = make_float4(f2tf(s[0]), f2tf(s[8]),
                                   f2tf(s[4 * RP]), f2tf(s[8 + 4 * RP]));
            float* d = (arr ? g_Fp : g_Ep) + (long)hh * RP * NSEQ + qh * 4;
            *(float4*)d = v;
        }
    }

    for (int s = 0; s < 16; s++) {
        if (s + 1 < 16) { cpwait<1>(); } else { cpwait<0>(); }
        __syncthreads();
        if (s + 2 < 16) load(s + 2);

        const float* A = sm + (s % 3) * QSTG;
        const float* B = A + 4096;
        #pragma unroll
        for (int ks = 0; ks < 4; ks++) {
            float4 a0 = *(const float4*)&A[((tmB    ) * 4 + ks) * 128 + lane * 4];
            float4 a1 = *(const float4*)&A[((tmB + 1) * 4 + ks) * 128 + lane * 4];
            #pragma unroll
            for (int nt = 0; nt < 8; nt++) {
                float2 bv = *(const float2*)&B[((tnB + nt) * 4 + ks) * 64 + lane * 2];
                mma_tf32(acc[0][nt], a0.x, a0.y, a0.z, a0.w, bv.x, bv.y);
                mma_tf32(acc[1][nt], a1.x, a1.y, a1.z, a1.w, bv.x, bv.y);
            }
        }
    }

    #pragma unroll
    for (int mt = 0; mt < 2; mt++)
    #pragma unroll
    for (int i = 0; i < 2; i++) {
        int m = m0t * 16 + (tmB + mt) * 16 + g + i * 8;
        int bb2 = m >> 12, ns = m & (NSEQ - 1);
        #pragma unroll
        for (int nt = 0; nt < 8; nt++) {
            int c = n0t * 8 + (tnB + nt) * 8 + tig * 2;
            int h = c >> 6, dh = c & 63;
            float v0 = f2tf(acc[mt][nt][i * 2]), v1 = f2tf(acc[mt][nt][i * 2 + 1]);
            long bhb = (long)(bb2 * HEADS + h);
            *(float2*)&outp[(bhb * NSEQ + ns) * DH + dh] = make_float2(v0, v1);
        }
    }
}

// =====================================================================
// fused_qproj: blocks 0..255 = proj (scheduled first), 256..1279 = qkv-Q.
// proj: KP/VP = E^T K / F^T V, packed-B outputs; qkv-Q: Q packed-A.
// =====================================================================
__global__ __launch_bounds__(256, 2) void fused_qproj()
{
    extern __shared__ float sm[];
    const int tid = threadIdx.x, wid = tid >> 5, lane = tid & 31;
    const int g = lane >> 2, tig = lane & 3;

    if (blockIdx.x < 256) {
        // ---------------- proj ----------------
        const int p = blockIdx.x;
        const int zz = p >> 7, rem = p & 127;
        const int bh = rem >> 1, h = bh & 7;
        const int r0t = (rem & 1) * 8;
        const float* Ap = (zz == 0 ? g_Ep : g_Fp) + (long)h * RP * NSEQ;
        const float* S  = (zz == 0 ? g_K : g_V) + (long)bh * NSEQ * DH;
        float* D = (zz == 0 ? g_KP : g_VP) + bh * RP * DH;

        const int tmB = (wid >> 1) * 2, wn = (wid & 1) * 32;
        float acc[2][4][4] = {};

        auto load = [&](int s) {
            float* buf = sm + (s % 3) * PSTG;
            uint32_t ab = s2u(buf), bb = s2u(buf + 4096);
            #pragma unroll
            for (int l = 0; l < 4; l++) {
                int q = l * 256 + tid, tl = q >> 7, r = q & 127;
                cpa16(ab + (tl * 512 + r * 4) * 4,
                      &Ap[(long)(r0t + tl) * 65536 + s * 512 + r * 4]);
            }
            #pragma unroll
            for (int l = 0; l < 2; l++) {
                int rr = l * 16 + (tid >> 4), c4 = (tid & 15) * 4;
                cpa16(bb + (rr * 72 + c4) * 4, &S[(long)(s * 32 + rr) * DH + c4]);
            }
            cpcommit();
        };

        load(0); load(1);
        for (int s = 0; s < 128; s++) {
            if (s + 1 < 128) { cpwait<1>(); } else { cpwait<0>(); }
            __syncthreads();
            if (s + 2 < 128) load(s + 2);

            const float* A = sm + (s % 3) * PSTG;
            const float* B = A + 4096;
            #pragma unroll
            for (int ks = 0; ks < 4; ks++) {
                int kb = ks * 8;
                float4 a0 = *(const float4*)&A[((tmB    ) * 4 + ks) * 128 + lane * 4];
                float4 a1 = *(const float4*)&A[((tmB + 1) * 4 + ks) * 128 + lane * 4];
                #pragma unroll
                for (int nt = 0; nt < 4; nt++) {
                    float b0 = B[(kb + tig)     * 72 + wn + nt * 8 + g];
                    float b1 = B[(kb + tig + 4) * 72 + wn + nt * 8 + g];
                    mma_tf32(acc[0][nt], a0.x, a0.y, a0.z, a0.w, b0, b1);
                    mma_tf32(acc[1][nt], a1.x, a1.y, a1.z, a1.w, b0, b1);
                }
            }
        }

        #pragma unroll
        for (int mt = 0; mt < 2; mt++)
        #pragma unroll
        for (int i = 0; i < 2; i++) {
            int r = r0t * 16 + (tmB + mt) * 16 + g + i * 8;
            #pragma unroll
            for (int nt = 0; nt < 4; nt++) {
                int c = wn + nt * 8 + tig * 2;
                float v0 = f2tf(acc[mt][nt][i * 2]), v1 = f2tf(acc[mt][nt][i * 2 + 1]);
                if (zz == 0) {
                    int q = ((r >> 3) * 8 + (c >> 3)) * 32 + (r & 7) * 4 + (c & 3);
                    int e = (c >> 2) & 1;
                    D[q * 2 + e] = v0;
                    D[(q + 1) * 2 + e] = v1;
                } else {
                    int q = ((c >> 3) * 32 + (r >> 3)) * 32 + (c & 7) * 4 + (r & 3);
                    int e = (r >> 2) & 1;
                    D[q * 2 + e] = v0;
                    D[q * 2 + e + 8] = v1;
                }
            }
        }
    } else {
        // ---------------- qkv-Q ----------------
        const int q = blockIdx.x - 256;
        const int m0t = (q >> 2) * 8;
        const int n0t = (q & 3) * 16;
        const float* wsrc = g_wp;

        const int tmB = (wid >> 1) * 2, tnB = (wid & 1) * 8;
        float acc[2][8][4] = {};

        auto load = [&](int s) {
            float* buf = sm + (s % 3) * QSTG;
            uint32_t ab = s2u(buf), bb = s2u(buf + 4096);
            #pragma unroll
            for (int l = 0; l < 4; l++) {
                int qq = l * 256 + tid, tl = qq >> 7, r = qq & 127;
                cpa16(ab + (tl * 512 + r * 4) * 4,
                      &g_xp[(long)(m0t + tl) * 8192 + s * 512 + r * 4]);
            }
            #pragma unroll
            for (int l = 0; l < 4; l++) {
                int qq = l * 256 + tid, tl = qq >> 6, r = qq & 63;
                cpa16(bb + (tl * 256 + r * 4) * 4,
                      &wsrc[(long)(n0t + tl) * 4096 + s * 256 + r * 4]);
            }
            cpcommit();
        };

        load(0); load(1);
        for (int s = 0; s < 16; s++) {
            if (s + 1 < 16) { cpwait<1>(); } else { cpwait<0>(); }
            __syncthreads();
            if (s + 2 < 16) load(s + 2);

            const float* A = sm + (s % 3) * QSTG;
            const float* B = A + 4096;
            #pragma unroll
            for (int ks = 0; ks < 4; ks++) {
                float4 a0 = *(const float4*)&A[((tmB    ) * 4 + ks) * 128 + lane * 4];
                float4 a1 = *(const float4*)&A[((tmB + 1) * 4 + ks) * 128 + lane * 4];
                #pragma unroll
                for (int nt = 0; nt < 8; nt++) {
                    float2 bv = *(const float2*)&B[((tnB + nt) * 4 + ks) * 64 + lane * 2];
                    mma_tf32(acc[0][nt], a0.x, a0.y, a0.z, a0.w, bv.x, bv.y);
                    mma_tf32(acc[1][nt], a1.x, a1.y, a1.z, a1.w, bv.x, bv.y);
                }
            }
        }

        #pragma unroll
        for (int mt = 0; mt < 2; mt++)
        #pragma unroll
        for (int i = 0; i < 2; i++) {
            int m = m0t * 16 + (tmB + mt) * 16 + g + i * 8;
            int bb2 = m >> 12, ns = m & (NSEQ - 1);
            #pragma unroll
            for (int nt = 0; nt < 8; nt++) {
                int c = n0t * 8 + (tnB + nt) * 8 + tig * 2;
                int h = c >> 6, dh = c & 63;
                float v0 = f2tf(acc[mt][nt][i * 2]), v1 = f2tf(acc[mt][nt][i * 2 + 1]);
                float* Qp = g_Q + (long)(bb2 * HEADS + h) * (NSEQ * DH);
                int qq = ((ns >> 4) * 8 + (dh >> 3)) * 32 + (ns & 7) * 4 + (dh & 3);
                int e = ((ns >> 3) & 1) + 2 * ((dh >> 2) & 1);
                Qp[qq * 4 + e] = v0;
                Qp[qq * 4 + e + 4] = v1;
            }
        }
    }
}

// =====================================================================
// attn: packed Q/KP/VP; double-buffered Q via cp.async.  grid (16, 64).
// =====================================================================
#define AT_QS 4096
#define AT_KP 16384
#define AT_VP 16384
#define AT_PS (64*260)
#define AT_SMEM ((2*AT_QS + AT_KP + AT_VP + AT_PS + 256)*4)

__global__ __launch_bounds__(256) void attn_kernel()
{
    extern __shared__ float sm[];
    float* Qs   = sm;
    float* kps  = Qs + 2 * AT_QS;
    float* vps  = kps + AT_KP;
    float* Ps   = vps + AT_VP;
    float* redM = Ps + AT_PS;
    float* redS = redM + 128;

    const int bh = blockIdx.y;
    const int tid = threadIdx.x;
    const int wid = tid >> 5, lane = tid & 31, g = lane >> 2, tig = lane & 3;
    const int wm = (wid >> 1) * 16, wn = wid & 1;
    const int tmq = wid >> 1;

    {
        const float* kpP = g_KP + (long)bh * RP * DH;
        const float* vpP = g_VP + (long)bh * RP * DH;
        #pragma unroll
        for (int l = 0; l < 16; l++) {
            int idx = (l * 256 + tid) * 4;
            *(float4*)&kps[idx] = *(const float4*)&kpP[idx];
            *(float4*)&vps[idx] = *(const float4*)&vpP[idx];
        }
    }

    const float* Qbase = g_Q + (long)bh * (NSEQ * DH) + (blockIdx.x * 256 >> 4) * 1024;
    {
        uint32_t qb = s2u(Qs);
        #pragma unroll
        for (int l = 0; l < 4; l++) {
            int idx = (l * 256 + tid) * 4;
            cpa16(qb + idx * 4, &Qbase[idx]);
        }
        cpcommit();
    }

    const int b = bh >> 3, h = bh & 7;
    const float scale = 0.125f;

    for (int ci = 0; ci < 4; ci++) {
        const int n0 = blockIdx.x * 256 + ci * 64;

        cpwait<0>();
        __syncthreads();

        if (ci + 1 < 4) {
            uint32_t qb = s2u(Qs + ((ci + 1) & 1) * AT_QS);
            const float* Qn = Qbase + (ci + 1) * AT_QS;
            #pragma unroll
            for (int l = 0; l < 4; l++) {
                int idx = (l * 256 + tid) * 4;
                cpa16(qb + idx * 4, &Qn[idx]);
            }
            cpcommit();
        }

        const float* Qc = Qs + (ci & 1) * AT_QS;

        float acc[16][4] = {};
        #pragma unroll
        for (int ks = 0; ks < 8; ks++) {
            float4 av = *(const float4*)&Qc[(tmq * 8 + ks) * 128 + lane * 4];
            #pragma unroll
            for (int nt = 0; nt < 16; nt++) {
                float2 bv = *(const float2*)&kps[((wn * 16 + nt) * 8 + ks) * 64 + lane * 2];
                mma_tf32(acc[nt], av.x, av.y, av.z, av.w, bv.x, bv.y);
            }
        }

        const int r0 = wm + g, r1 = r0 + 8;
        float mx0 = -1e30f, mx1 = -1e30f;
        #pragma unroll
        for (int nt = 0; nt < 16; nt++) {
            mx0 = fmaxf(mx0, fmaxf(acc[nt][0], acc[nt][1]));
            mx1 = fmaxf(mx1, fmaxf(acc[nt][2], acc[nt][3]));
        }
        mx0 = fmaxf(mx0, __shfl_xor_sync(0xffffffffu, mx0, 1));
        mx0 = fmaxf(mx0, __shfl_xor_sync(0xffffffffu, mx0, 2));
        mx1 = fmaxf(mx1, __shfl_xor_sync(0xffffffffu, mx1, 1));
        mx1 = fmaxf(mx1, __shfl_xor_sync(0xffffffffu, mx1, 2));
        if (tig == 0) { redM[r0 * 2 + wn] = mx0; redM[r1 * 2 + wn] = mx1; }
        __syncthreads();
        mx0 = fmaxf(redM[r0 * 2], redM[r0 * 2 + 1]) * scale;
        mx1 = fmaxf(redM[r1 * 2], redM[r1 * 2 + 1]) * scale;

        float s0 = 0.f, s1 = 0.f;
        #pragma unroll
        for (int nt = 0; nt < 16; nt++) {
            int c = wn * 128 + nt * 8 + tig * 2;
            float e0 = __expf(acc[nt][0] * scale - mx0);
            float e1 = __expf(acc[nt][1] * scale - mx0);
            s0 += e0 + e1;
            *(float2*)&Ps[r0 * 260 + c] = make_float2(f2tf(e0), f2tf(e1));
            float e2 = __expf(acc[nt][2] * scale - mx1);
            float e3 = __expf(acc[nt][3] * scale - mx1);
            s1 += e2 + e3;
            *(float2*)&Ps[r1 * 260 + c] = make_float2(f2tf(e2), f2tf(e3));
        }
        s0 += __shfl_xor_sync(0xffffffffu, s0, 1);
        s0 += __shfl_xor_sync(0xffffffffu, s0, 2);
        s1 += __shfl_xor_sync(0xffffffffu, s1, 1);
        s1 += __shfl_xor_sync(0xffffffffu, s1, 2);
        if (tig == 0) { redS[r0 * 2 + wn] = s0; redS[r1 * 2 + wn] = s1; }
        __syncthreads();

        float acc2[4][4] = {};
        #pragma unroll 8
        for (int ks = 0; ks < 32; ks++) {
            int kb = ks * 8;
            float a0 = Ps[(wm + g)     * 260 + kb + tig];
            float a1 = Ps[(wm + g + 8) * 260 + kb + tig];
            float a2 = Ps[(wm + g)     * 260 + kb + tig + 4];
            float a3 = Ps[(wm + g + 8) * 260 + kb + tig + 4];
            #pragma unroll
            for (int nt = 0; nt < 4; nt++) {
                float2 bv = *(const float2*)&vps[((wn * 4 + nt) * 32 + ks) * 64 + lane * 2];
                mma_tf32(acc2[nt], a0, a1, a2, a3, bv.x, bv.y);
            }
        }

        const float inv0 = __frcp_rn(redS[r0 * 2] + redS[r0 * 2 + 1]);
        const float inv1 = __frcp_rn(redS[r1 * 2] + redS[r1 * 2 + 1]);
        float* ao = g_AO + (long)(b * NSEQ + n0) * DM + h * DH;
        #pragma unroll
        for (int nt = 0; nt < 4; nt++) {
            int c = wn * 32 + nt * 8 + tig * 2;
            *(float2*)&ao[r0 * DM + c] =
                make_float2(f2tf(acc2[nt][0] * inv0), f2tf(acc2[nt][1] * inv0));
            *(float2*)&ao[r1 * DM + c] =
                make_float2(f2tf(acc2[nt][2] * inv1), f2tf(acc2[nt][3] * inv1));
        }
    }
}

// =====================================================================
// outproj: A raw pre-tf32 AO, B packed wo.  Single barrier per stage.
// =====================================================================
#define OA 4608
#define OSTG (OA + 4096)
#define OUT_SMEM (3*OSTG*4)

__global__ __launch_bounds__(256, 2) void outproj_kernel(
    const float* __restrict__ bo, float* __restrict__ out)
{
    extern __shared__ float sm[];
    const float* wsrc = g_wp + 3 * DM * DM;

    const int m0 = blockIdx.y * 128, n0t = blockIdx.x * 16;
    const int tid = threadIdx.x, wid = tid >> 5, lane = tid & 31;
    const int g = lane >> 2, tig = lane & 3;
    const int wm = (wid >> 1) * 32, tnB = (wid & 1) * 8;

    float acc[2][8][4] = {};

    auto load = [&](int s) {
        float* buf = sm + (s % 3) * OSTG;
        uint32_t ab = s2u(buf), bb = s2u(buf + OA);
        int k0 = s * 32;
        #pragma unroll
        for (int l = 0; l < 4; l++) {
            int r = l * 32 + (tid >> 3), c4 = (tid & 7) * 4;
            cpa16(ab + (r * 36 + c4) * 4, &g_AO[(long)(m0 + r) * DM + k0 + c4]);
        }
        #pragma unroll
        for (int l = 0; l < 4; l++) {
            int q = l * 256 + tid, tl = q >> 6, r = q & 63;
            cpa16(bb + (tl * 256 + r * 4) * 4, &wsrc[(long)(n0t + tl) * 4096 + s * 256 + r * 4]);
        }
        cpcommit();
    };

    load(0); load(1);
    for (int s = 0; s < 16; s++) {
        if (s + 1 < 16) { cpwait<1>(); } else { cpwait<0>(); }
        __syncthreads();
        if (s + 2 < 16) load(s + 2);

        const float* A = sm + (s % 3) * OSTG;
        const float* B = A + OA;
        #pragma unroll
        for (int ks = 0; ks < 4; ks++) {
            int kb = ks * 8;
            float a[2][4];
            #pragma unroll
            for (int mt = 0; mt < 2; mt++) {
                int r = wm + mt * 16;
                a[mt][0] = A[(r + g)     * 36 + kb + tig];
                a[mt][1] = A[(r + g + 8) * 36 + kb + tig];
                a[mt][2] = A[(r + g)     * 36 + kb + tig + 4];
                a[mt][3] = A[(r + g + 8) * 36 + kb + tig + 4];
            }
            #pragma unroll
            for (int nt = 0; nt < 8; nt++) {
                float2 bv = *(const float2*)&B[((tnB + nt) * 4 + ks) * 64 + lane * 2];
                mma_tf32(acc[0][nt], a[0][0], a[0][1], a[0][2], a[0][3], bv.x, bv.y);
                mma_tf32(acc[1][nt], a[1][0], a[1][1], a[1][2], a[1][3], bv.x, bv.y);
            }
        }
    }

    #pragma unroll
    for (int mt = 0; mt < 2; mt++)
    #pragma unroll
    for (int i = 0; i < 2; i++) {
        int m = m0 + wm + mt * 16 + g + i * 8;
        #pragma unroll
        for (int nt = 0; nt < 8; nt++) {
            int c = n0t * 8 + (tnB + nt) * 8 + tig * 2;
            float2 bias = *(const float2*)&bo[c];
            *(float2*)&out[(long)m * DM + c] =
                make_float2(acc[mt][nt][i * 2] + bias.x, acc[mt][nt][i * 2 + 1] + bias.y);
        }
    }
}

// =====================================================================
extern "C" void kernel_launch(void* const* d_in, const int* in_sizes, int n_in,
                              void* d_out, int out_size)
{
    (void)in_sizes; (void)n_in; (void)out_size;
    const float* x  = (const float*)d_in[0];
    const float* wq = (const float*)d_in[1];
    const float* wk = (const float*)d_in[2];
    const float* wv = (const float*)d_in[3];
    const float* E  = (const float*)d_in[4];
    const float* F  = (const float*)d_in[5];
    const float* wo = (const float*)d_in[6];
    const float* bo = (const float*)d_in[7];
    float* out = (float*)d_out;

    cudaFuncSetAttribute(qkv_kv,         cudaFuncAttributeMaxDynamicSharedMemorySize, QKV_SMEM);
    cudaFuncSetAttribute(fused_qproj,    cudaFuncAttributeMaxDynamicSharedMemorySize, QKV_SMEM);
    cudaFuncSetAttribute(attn_kernel,    cudaFuncAttributeMaxDynamicSharedMemorySize, AT_SMEM);
    cudaFuncSetAttribute(outproj_kernel, cudaFuncAttributeMaxDynamicSharedMemorySize, OUT_SMEM);

    float *p_xp, *p_wp;
    cudaGetSymbolAddress((void**)&p_xp, g_xp);
    cudaGetSymbolAddress((void**)&p_wp, g_wp);

    pack_a<<<MTOT*DM/1024, 256>>>(x, p_xp, 64, DM, 1, 0, 0);
    pack_b<<<dim3(DM*DM/512, 2), 256>>>(wq, wk, p_wp,            64, DM);
    pack_b<<<dim3(DM*DM/512, 2), 256>>>(wv, wo, p_wp + 2*DM*DM,  64, DM);

    qkv_kv        <<<dim3(4, 256, 2), 256, QKV_SMEM>>>(E, F);
    fused_qproj   <<<1280,            256, QKV_SMEM>>>();
    attn_kernel   <<<dim3(16, 64),    256, AT_SMEM>>>();
    outproj_kernel<<<dim3(4, 256),    256, OUT_SMEM>>>(bo, out);
}